// round 11
// baseline (speedup 1.0000x reference)
#include <cuda_runtime.h>
#include <cstdint>
#include <cstddef>

#define BB 64
#define TT 512
#define II 1024
#define HH 1024

typedef unsigned long long ull;

// ---------------- scratch (device globals; no cudaMalloc allowed) ----------------
__device__ float g_xw[(size_t)BB * TT * HH];   // 128 MiB: xw = x@W^T + bW
__device__ float g_h3[2][(size_t)BB * HH];     // ping-pong h3 exchange
__device__ unsigned g_cnt[128];                // per-b-group counters (slot bt*32)

// ---------------- helpers ----------------
__device__ __forceinline__ void ffma2(ull &d, ull a, ull b) {
    asm("fma.rn.f32x2 %0, %1, %2, %0;" : "+l"(d) : "l"(a), "l"(b));
}
__device__ __forceinline__ float lohi_sum(ull v) {
    float lo, hi;
    asm("mov.b64 {%0, %1}, %2;" : "=f"(lo), "=f"(hi) : "l"(v));
    return lo + hi;
}
__device__ __forceinline__ float hw_tanh(float x) {
    float r;
    asm("tanh.approx.f32 %0, %1;" : "=f"(r) : "f"(x));
    return r;
}

// =====================================================================
// Kernel 1: xw = x @ W^T + bW. (unchanged; + counter reset)
// =====================================================================
#define G_STR 36

__global__ __launch_bounds__(256, 2) void gemm1_kernel(
    const float* __restrict__ x, const float* __restrict__ W,
    const float* __restrict__ bW)
{
    if (blockIdx.x == 0 && blockIdx.y == 0 && threadIdx.x < 128)
        g_cnt[threadIdx.x] = 0u;

    __shared__ float As[2][64 * G_STR];
    __shared__ float Bs[2][64 * G_STR];

    const int tid = threadIdx.x;
    const int m_blk = blockIdx.y * 64, n_blk = blockIdx.x * 64;
    const int w = tid >> 5, l = tid & 31;
    const int wm = (w & 3) * 16, wn = (w >> 2) * 32;
    const int lm = l & 3, ln = l >> 2;
    const int lrow = tid >> 2, lcol = (tid & 3) * 4;

    const float* xp = &x[(size_t)(m_blk + lrow) * II + lcol];
    const float* wp = &W[(size_t)(n_blk + lrow) * II + lcol];

    ull acc[4][4];
#pragma unroll
    for (int i = 0; i < 4; ++i)
#pragma unroll
        for (int j = 0; j < 4; ++j) acc[i][j] = 0ULL;

    {
        float4 xa = *(const float4*)xp;
        float4 xb = *(const float4*)(xp + 16);
        float4 wa = *(const float4*)wp;
        float4 wb = *(const float4*)(wp + 16);
        *(float4*)&As[0][lrow * G_STR + lcol]      = xa;
        *(float4*)&As[0][lrow * G_STR + lcol + 16] = xb;
        *(float4*)&Bs[0][lrow * G_STR + lcol]      = wa;
        *(float4*)&Bs[0][lrow * G_STR + lcol + 16] = wb;
    }
    __syncthreads();

    for (int it = 0; it < II / 32; ++it) {
        const int cur = it & 1, nxt = cur ^ 1;
        float4 xa, xb, wa, wb;
        const bool more = (it + 1) < II / 32;
        if (more) {
            const int kk = (it + 1) * 32;
            xa = *(const float4*)(xp + kk);
            xb = *(const float4*)(xp + kk + 16);
            wa = *(const float4*)(wp + kk);
            wb = *(const float4*)(wp + kk + 16);
        }
#pragma unroll
        for (int kq = 0; kq < 8; ++kq) {
            ulonglong2 a[4], b[4];
#pragma unroll
            for (int i = 0; i < 4; ++i)
                a[i] = *(const ulonglong2*)&As[cur][(wm + lm + 4 * i) * G_STR + kq * 4];
#pragma unroll
            for (int j = 0; j < 4; ++j)
                b[j] = *(const ulonglong2*)&Bs[cur][(wn + ln + 8 * j) * G_STR + kq * 4];
#pragma unroll
            for (int i = 0; i < 4; ++i)
#pragma unroll
                for (int j = 0; j < 4; ++j) {
                    ffma2(acc[i][j], a[i].x, b[j].x);
                    ffma2(acc[i][j], a[i].y, b[j].y);
                }
        }
        if (more) {
            *(float4*)&As[nxt][lrow * G_STR + lcol]      = xa;
            *(float4*)&As[nxt][lrow * G_STR + lcol + 16] = xb;
            *(float4*)&Bs[nxt][lrow * G_STR + lcol]      = wa;
            *(float4*)&Bs[nxt][lrow * G_STR + lcol + 16] = wb;
        }
        __syncthreads();
    }

    float bwv[4];
#pragma unroll
    for (int j = 0; j < 4; ++j) bwv[j] = bW[n_blk + wn + ln + 8 * j];
#pragma unroll
    for (int i = 0; i < 4; ++i) {
        const size_t row = (size_t)(m_blk + wm + lm + 4 * i) * HH + n_blk + wn + ln;
#pragma unroll
        for (int j = 0; j < 4; ++j)
            g_xw[row + 8 * j] = lohi_sum(acc[i][j]) + bwv[j];
    }
}

// =====================================================================
// Kernel 2: persistent scan, 4b x 4n microtile + warp-local staging.
// 128 CTAs = 4 b-groups x 32 n-tiles, 512 threads (16 warps).
// Warp w owns k-chunk [64w, 64w+64). Lane (lb=l&3, ln=l>>2) owns
// microtile b in {lb,lb+4,lb+8,lb+12} x n in {ln,ln+8,ln+16,ln+24}:
// per k-quad 8 LDS.128 : 32 FFMA2. Each warp stages its own h3 slice
// (syncwarp only). 16 k-partials reduced via swizzled red.
// =====================================================================
#define U_STR 1028                 // 16B-group = n mod 8 -> conflict-free u
#define H_STR 1032                 // 16B-group = 2b mod 8 -> conflict-free h
#define RED_OFF (32 * U_STR + 16 * H_STR)          // 49408 floats
#define SMEM_SCAN ((RED_OFF + 16 * 512) * 4)       // 230400 bytes

__global__ __launch_bounds__(512, 1) void scan_kernel(
    const float* __restrict__ U, const float* __restrict__ bU,
    float* __restrict__ out1, float* __restrict__ out2)
{
    extern __shared__ float smem[];
    float* Us  = smem;               // [32][U_STR]
    float* h3s = smem + 32 * U_STR;  // [16][H_STR]
    float* red = smem + RED_OFF;     // [16][16][32] XOR-swizzled

    const int tid = threadIdx.x;
    const int bt = blockIdx.x >> 5, nt = blockIdx.x & 31;
    const int b0 = bt * 16, n0 = nt * 32;
    unsigned* cnt = &g_cnt[bt * 32];

    // load U slice (rows n0..n0+31) once
    for (int i = tid; i < 32 * 256; i += 512) {
        int r = i >> 8, c = (i & 255) * 4;
        *(float4*)&Us[r * U_STR + c] = *(const float4*)&U[(size_t)(n0 + r) * HH + c];
    }

    const int w = tid >> 5, l = tid & 31;
    const int lb = l & 3, ln = l >> 2;
    const int k0 = w * 64;                 // this warp's k-chunk

    // staging map: warp covers 16 rows x 16 float4 cols of its chunk;
    // lane handles 8 (row, c4) pairs: idx = i*32 + l
    // output mapping: one element per thread
    const int bi = tid >> 5;               // 0..15
    const int nl = tid & 31;               // 0..31
    const float bu = bU[n0 + nl];
    const unsigned orow = (unsigned)(b0 + bi) * TT * HH + n0 + nl;
    const unsigned hrow = (unsigned)(b0 + bi) * HH + n0 + nl;
    const int rcol = (nl + 8 * bi) & 31;   // swizzled read column

    // ---- bootstrap: h3[0] = tanh(xw[0]) ----
    {
        float h = hw_tanh(g_xw[orow]);
        g_h3[0][hrow] = h;
        out1[orow] = h;
    }
    __syncthreads();
    if (tid == 0) { __threadfence(); atomicAdd(cnt, 1u); }

    for (int t = 0; t < TT - 1; ++t) {
        // prefetch xw[t+1] (issues before the barrier wait)
        const float xwv = g_xw[orow + (unsigned)(t + 1) * HH];

        // ---- wait for h3[t] from all 32 CTAs of this b-group ----
        if (tid == 0) {
            const unsigned target = 32u * (unsigned)(t + 1);
            while (*(volatile unsigned*)cnt < target) {}
            __threadfence();
        }
        __syncthreads();

        // ---- warp-local staging: this warp's 16b x 64k slice ----
        {
            const float* hsrc = &g_h3[t & 1][(size_t)b0 * HH + k0];
#pragma unroll
            for (int i = 0; i < 8; ++i) {
                const int idx = i * 32 + l;
                const int row = idx >> 4, c4 = (idx & 15) * 4;
                float4 hv = *(const float4*)&hsrc[(size_t)row * HH + c4];
                *(float4*)&h3s[row * H_STR + k0 + c4] = hv;
            }
        }
        __syncwarp();

        // ---- Phase B: 4b x 4n microtile over this warp's k-chunk ----
        ull acc[4][4];
#pragma unroll
        for (int i = 0; i < 4; ++i)
#pragma unroll
            for (int j = 0; j < 4; ++j) acc[i][j] = 0ULL;

#pragma unroll 4
        for (int kq = 0; kq < 16; ++kq) {
            const int k = k0 + kq * 4;
            ulonglong2 hq[4], uq[4];
#pragma unroll
            for (int i = 0; i < 4; ++i)
                hq[i] = *(const ulonglong2*)&h3s[(lb + 4 * i) * H_STR + k];
#pragma unroll
            for (int j = 0; j < 4; ++j)
                uq[j] = *(const ulonglong2*)&Us[(ln + 8 * j) * U_STR + k];
#pragma unroll
            for (int i = 0; i < 4; ++i)
#pragma unroll
                for (int j = 0; j < 4; ++j) {
                    ffma2(acc[i][j], hq[i].x, uq[j].x);
                    ffma2(acc[i][j], hq[i].y, uq[j].y);
                }
        }

        // swizzled conflict-free partial stores: col' = (col + 8*row) & 31
#pragma unroll
        for (int i = 0; i < 4; ++i) {
            const int row = lb + 4 * i;
#pragma unroll
            for (int j = 0; j < 4; ++j) {
                const int col = ln + 8 * j;
                red[w * 512 + row * 32 + ((col + 8 * row) & 31)] =
                    lohi_sum(acc[i][j]);
            }
        }
        __syncthreads();

        // ---- reduce 16 warp-partials (2 chains), fuse, publish ----
        {
            float s0 = bu, s1 = 0.0f;
#pragma unroll
            for (int p = 0; p < 16; p += 2) {
                s0 += red[p * 512 + bi * 32 + rcol];
                s1 += red[(p + 1) * 512 + bi * 32 + rcol];
            }
            const float h = hw_tanh(s0 + s1 + xwv);
            g_h3[(t + 1) & 1][hrow] = h;
            out1[orow + (unsigned)(t + 1) * HH] = h;
            if (t == TT - 2) out2[hrow] = h;
        }
        __syncthreads();
        if (tid == 0) { __threadfence(); atomicAdd(cnt, 1u); }
    }
}

// =====================================================================
// launch
// =====================================================================
extern "C" void kernel_launch(void* const* d_in, const int* in_sizes, int n_in,
                              void* d_out, int out_size)
{
    const float* x  = (const float*)d_in[0];
    const float* W  = (const float*)d_in[1];
    const float* bW = (const float*)d_in[2];
    const float* U  = (const float*)d_in[3];
    const float* bU = (const float*)d_in[4];

    float* out1 = (float*)d_out;
    float* out2 = out1 + (size_t)BB * TT * HH;

    cudaFuncSetAttribute(scan_kernel,
                         cudaFuncAttributeMaxDynamicSharedMemorySize, SMEM_SCAN);

    dim3 g1(HH / 64, (BB * TT) / 64);   // (16, 512)
    gemm1_kernel<<<g1, 256>>>(x, W, bW);
    scan_kernel<<<128, 512, SMEM_SCAN>>>(U, bU, out1, out2);
}

// round 13
// speedup vs baseline: 1.8419x; 1.8419x over previous
#include <cuda_runtime.h>
#include <cuda_bf16.h>
#include <cstdint>
#include <cstddef>

#define BB 64
#define TT 512
#define II 1024
#define HH 1024

typedef unsigned long long ull;

// ---------------- scratch (device globals; no cudaMalloc allowed) ----------------
__device__ float g_xw[(size_t)BB * TT * HH];   // 128 MiB: xw = x@W^T + bW
__device__ float g_h3[2][(size_t)BB * HH];     // ping-pong h3 exchange
__device__ unsigned g_cnt[128];                // per-b-group counters (slot bt*32)
__device__ __nv_bfloat16 g_xhi[(size_t)BB * TT * II];
__device__ __nv_bfloat16 g_xlo[(size_t)BB * TT * II];
__device__ __nv_bfloat16 g_whi[(size_t)HH * II];
__device__ __nv_bfloat16 g_wlo[(size_t)HH * II];

// ---------------- helpers ----------------
__device__ __forceinline__ float hw_tanh(float x) {
    float r;
    asm("tanh.approx.f32 %0, %1;" : "=f"(r) : "f"(x));
    return r;
}
__device__ __forceinline__ void ffma2(ull &d, ull a, ull b) {
    asm("fma.rn.f32x2 %0, %1, %2, %0;" : "+l"(d) : "l"(a), "l"(b));
}
__device__ __forceinline__ float lohi_sum(ull v) {
    float lo, hi;
    asm("mov.b64 {%0, %1}, %2;" : "=f"(lo), "=f"(hi) : "l"(v));
    return lo + hi;
}
// HMMA m16n8k16 bf16 row.col, f32 accumulate (sm_80+ path; legal on sm_103)
__device__ __forceinline__ void mma16816(float* c, const uint32_t* a, const uint32_t* b) {
    asm volatile(
        "mma.sync.aligned.m16n8k16.row.col.f32.bf16.bf16.f32 "
        "{%0,%1,%2,%3}, {%4,%5,%6,%7}, {%8,%9}, {%0,%1,%2,%3};"
        : "+f"(c[0]), "+f"(c[1]), "+f"(c[2]), "+f"(c[3])
        : "r"(a[0]), "r"(a[1]), "r"(a[2]), "r"(a[3]), "r"(b[0]), "r"(b[1]));
}

// =====================================================================
// Kernel 0: split x and W into hi/lo bf16; reset barrier counters.
// =====================================================================
__global__ __launch_bounds__(256) void split_kernel(
    const float* __restrict__ x, const float* __restrict__ W)
{
    if (blockIdx.x == 0 && threadIdx.x < 128) g_cnt[threadIdx.x] = 0u;
    const size_t stride = (size_t)gridDim.x * blockDim.x;
    const size_t i0 = (size_t)blockIdx.x * blockDim.x + threadIdx.x;

    const size_t NX4 = (size_t)BB * TT * II / 4;
    for (size_t p = i0; p < NX4; p += stride) {
        float4 v = ((const float4*)x)[p];
        __nv_bfloat16 h0 = __float2bfloat16(v.x), h1 = __float2bfloat16(v.y);
        __nv_bfloat16 h2 = __float2bfloat16(v.z), h3 = __float2bfloat16(v.w);
        __nv_bfloat16 l0 = __float2bfloat16(v.x - __bfloat162float(h0));
        __nv_bfloat16 l1 = __float2bfloat16(v.y - __bfloat162float(h1));
        __nv_bfloat16 l2 = __float2bfloat16(v.z - __bfloat162float(h2));
        __nv_bfloat16 l3 = __float2bfloat16(v.w - __bfloat162float(h3));
        ((__nv_bfloat162*)g_xhi)[2 * p]     = __nv_bfloat162(h0, h1);
        ((__nv_bfloat162*)g_xhi)[2 * p + 1] = __nv_bfloat162(h2, h3);
        ((__nv_bfloat162*)g_xlo)[2 * p]     = __nv_bfloat162(l0, l1);
        ((__nv_bfloat162*)g_xlo)[2 * p + 1] = __nv_bfloat162(l2, l3);
    }
    const size_t NW4 = (size_t)HH * II / 4;
    for (size_t p = i0; p < NW4; p += stride) {
        float4 v = ((const float4*)W)[p];
        __nv_bfloat16 h0 = __float2bfloat16(v.x), h1 = __float2bfloat16(v.y);
        __nv_bfloat16 h2 = __float2bfloat16(v.z), h3 = __float2bfloat16(v.w);
        __nv_bfloat16 l0 = __float2bfloat16(v.x - __bfloat162float(h0));
        __nv_bfloat16 l1 = __float2bfloat16(v.y - __bfloat162float(h1));
        __nv_bfloat16 l2 = __float2bfloat16(v.z - __bfloat162float(h2));
        __nv_bfloat16 l3 = __float2bfloat16(v.w - __bfloat162float(h3));
        ((__nv_bfloat162*)g_whi)[2 * p]     = __nv_bfloat162(h0, h1);
        ((__nv_bfloat162*)g_whi)[2 * p + 1] = __nv_bfloat162(h2, h3);
        ((__nv_bfloat162*)g_wlo)[2 * p]     = __nv_bfloat162(l0, l1);
        ((__nv_bfloat162*)g_wlo)[2 * p + 1] = __nv_bfloat162(l2, l3);
    }
}

// =====================================================================
// Kernel 1: xw = x@W^T + bW via mma.sync bf16, hi/lo split (hh+hl+lh).
// CTA 128m x 128n, 256 threads = 8 warps (2m x 4n), warp tile 64x32.
// K = 3 terms x 1024 = 3072, BK=32 double-buffered (96 iters).
// Fragments loaded with plain LDS.32 (row.col layout makes both A and B
// lane-contiguous in K-major rows). Smem row stride 40 bf16: fragment
// banks (g*20 + t) mod 32 all distinct -> conflict-free.
// =====================================================================
#define MS 40   // smem row stride in bf16

__global__ __launch_bounds__(256, 2) void mma_kernel(const float* __restrict__ bW)
{
    __shared__ __nv_bfloat16 sA[2][128 * MS];
    __shared__ __nv_bfloat16 sB[2][128 * MS];

    const int tid = threadIdx.x;
    const int wid = tid >> 5, l = tid & 31;
    const int g = l >> 2, t = l & 3;          // fragment lane coords
    const int wm = (wid & 1) * 64;            // warp m base (0/64)
    const int wn = (wid >> 1) * 32;           // warp n base (0..96)
    const int n_blk = blockIdx.x * 128, m_blk = blockIdx.y * 128;

    const __nv_bfloat16* Aptr[3] = { g_xhi, g_xhi, g_xlo };
    const __nv_bfloat16* Bptr[3] = { g_whi, g_wlo, g_whi };

    // staging map: idx = i*256 + tid -> row = idx>>2 (0..127), gr = idx&3
    const int ar0 = tid >> 2, ag0 = (tid & 3) * 8;
    const int ar1 = (tid + 256) >> 2, ag1 = ag0;   // same granule, +64 rows

    float acc[4][4][4];
#pragma unroll
    for (int i = 0; i < 4; ++i)
#pragma unroll
        for (int j = 0; j < 4; ++j)
#pragma unroll
            for (int q = 0; q < 4; ++q) acc[i][j][q] = 0.0f;

    // preload stage 0 (term 0, ko 0)
    {
        const __nv_bfloat16* ap = Aptr[0] + (size_t)m_blk * II;
        const __nv_bfloat16* bp = Bptr[0] + (size_t)n_blk * II;
        *(uint4*)&sA[0][ar0 * MS + ag0] = *(const uint4*)(ap + (size_t)ar0 * II + ag0);
        *(uint4*)&sA[0][ar1 * MS + ag1] = *(const uint4*)(ap + (size_t)ar1 * II + ag1);
        *(uint4*)&sB[0][ar0 * MS + ag0] = *(const uint4*)(bp + (size_t)ar0 * II + ag0);
        *(uint4*)&sB[0][ar1 * MS + ag1] = *(const uint4*)(bp + (size_t)ar1 * II + ag1);
    }
    __syncthreads();

    for (int c = 0; c < 96; ++c) {
        const int cur = c & 1, nxt = cur ^ 1;
        uint4 va0, va1, vb0, vb1;
        const bool more = (c + 1) < 96;
        if (more) {
            const int term = (c + 1) >> 5;
            const int ko = ((c + 1) & 31) * 32;
            const __nv_bfloat16* ap = Aptr[term] + (size_t)m_blk * II + ko;
            const __nv_bfloat16* bp = Bptr[term] + (size_t)n_blk * II + ko;
            va0 = *(const uint4*)(ap + (size_t)ar0 * II + ag0);
            va1 = *(const uint4*)(ap + (size_t)ar1 * II + ag1);
            vb0 = *(const uint4*)(bp + (size_t)ar0 * II + ag0);
            vb1 = *(const uint4*)(bp + (size_t)ar1 * II + ag1);
        }

        // compute: two k16 steps over the current 32-wide buffer
#pragma unroll
        for (int ks = 0; ks < 2; ++ks) {
            const int kk = ks * 16;
            uint32_t af[4][4], bf[4][2];
#pragma unroll
            for (int mt = 0; mt < 4; ++mt) {
                const int row = wm + 16 * mt + g;
                af[mt][0] = *(const uint32_t*)&sA[cur][row * MS + kk + 2 * t];
                af[mt][1] = *(const uint32_t*)&sA[cur][(row + 8) * MS + kk + 2 * t];
                af[mt][2] = *(const uint32_t*)&sA[cur][row * MS + kk + 2 * t + 8];
                af[mt][3] = *(const uint32_t*)&sA[cur][(row + 8) * MS + kk + 2 * t + 8];
            }
#pragma unroll
            for (int nt = 0; nt < 4; ++nt) {
                const int rn = wn + 8 * nt + g;
                bf[nt][0] = *(const uint32_t*)&sB[cur][rn * MS + kk + 2 * t];
                bf[nt][1] = *(const uint32_t*)&sB[cur][rn * MS + kk + 2 * t + 8];
            }
#pragma unroll
            for (int mt = 0; mt < 4; ++mt)
#pragma unroll
                for (int nt = 0; nt < 4; ++nt)
                    mma16816(acc[mt][nt], af[mt], bf[nt]);
        }

        if (more) {
            *(uint4*)&sA[nxt][ar0 * MS + ag0] = va0;
            *(uint4*)&sA[nxt][ar1 * MS + ag1] = va1;
            *(uint4*)&sB[nxt][ar0 * MS + ag0] = vb0;
            *(uint4*)&sB[nxt][ar1 * MS + ag1] = vb1;
        }
        __syncthreads();
    }

    // ---- epilogue: add bW, store fp32 ----
#pragma unroll
    for (int nt = 0; nt < 4; ++nt) {
        const int col = n_blk + wn + 8 * nt + 2 * t;
        const float2 bw2 = *(const float2*)&bW[col];
#pragma unroll
        for (int mt = 0; mt < 4; ++mt) {
            const int m0 = m_blk + wm + 16 * mt + g;
            float2 o0, o1;
            o0.x = acc[mt][nt][0] + bw2.x; o0.y = acc[mt][nt][1] + bw2.y;
            o1.x = acc[mt][nt][2] + bw2.x; o1.y = acc[mt][nt][3] + bw2.y;
            *(float2*)&g_xw[(size_t)m0 * HH + col] = o0;
            *(float2*)&g_xw[(size_t)(m0 + 8) * HH + col] = o1;
        }
    }
}

// =====================================================================
// Kernel 2: persistent scan — EXACT R7 code (proven 3.544 ms).
// =====================================================================
#define U_STR 1028
#define H_STR 1032
#define RED_OFF (32 * U_STR + 16 * H_STR)
#define R_STR 40
#define SMEM_SCAN ((RED_OFF + 8 * 16 * R_STR) * 4)   // 218112 bytes

__global__ __launch_bounds__(512, 1) void scan_kernel(
    const float* __restrict__ U, const float* __restrict__ bU,
    float* __restrict__ out1, float* __restrict__ out2)
{
    extern __shared__ float smemf[];
    float* Us  = smemf;
    float* h3s = smemf + 32 * U_STR;
    float* red = smemf + RED_OFF;

    const int tid = threadIdx.x;
    const int bt = blockIdx.x >> 5, nt = blockIdx.x & 31;
    const int b0 = bt * 16, n0 = nt * 32;
    unsigned* cnt = &g_cnt[bt * 32];

    for (int i = tid; i < 32 * 256; i += 512) {
        int r = i >> 8, c = (i & 255) * 4;
        *(float4*)&Us[r * U_STR + c] = *(const float4*)&U[(size_t)(n0 + r) * HH + c];
    }

    const int bi = tid >> 5;
    const int nl = tid & 31;
    const float bu = bU[n0 + nl];
    const size_t orow = (size_t)(b0 + bi) * TT * HH + n0 + nl;
    const size_t hrow = (size_t)(b0 + bi) * HH + n0 + nl;

    const int w = tid >> 5, l = tid & 31;
    const int wk = w >> 1;
    const int wb = (w & 1) * 8;
    const int lb = l & 3, ln = l >> 2;
    const int k0 = wk * 128;

    {
        float h = hw_tanh(g_xw[orow]);
        g_h3[0][hrow] = h;
        out1[orow] = h;
    }
    __syncthreads();
    if (tid == 0) { __threadfence(); atomicAdd(cnt, 1u); }

    for (int t = 0; t < TT - 1; ++t) {
        if (tid == 0) {
            const unsigned target = 32u * (unsigned)(t + 1);
            while (*(volatile unsigned*)cnt < target) {}
            __threadfence();
        }
        __syncthreads();

        const float xwv = g_xw[orow + (size_t)(t + 1) * HH];

        {
            const float* hsrc = &g_h3[t & 1][(size_t)b0 * HH];
#pragma unroll
            for (int r = 0; r < 8; ++r) {
                float4 hv = *(const float4*)&hsrc[(size_t)(wb + r) * HH + k0 + l * 4];
                *(float4*)&h3s[(wb + r) * H_STR + k0 + l * 4] = hv;
            }
        }
        __syncwarp();

        ull acc[2][4];
#pragma unroll
        for (int i = 0; i < 2; ++i)
#pragma unroll
            for (int jj = 0; jj < 4; ++jj) acc[i][jj] = 0ULL;

#pragma unroll 4
        for (int kq = 0; kq < 32; ++kq) {
            const int k = k0 + kq * 4;
            ulonglong2 hv0 = *(const ulonglong2*)&h3s[(wb + lb) * H_STR + k];
            ulonglong2 hv1 = *(const ulonglong2*)&h3s[(wb + lb + 4) * H_STR + k];
            ulonglong2 uv[4];
#pragma unroll
            for (int jj = 0; jj < 4; ++jj)
                uv[jj] = *(const ulonglong2*)&Us[(ln + 8 * jj) * U_STR + k];
#pragma unroll
            for (int jj = 0; jj < 4; ++jj) {
                ffma2(acc[0][jj], hv0.x, uv[jj].x);
                ffma2(acc[0][jj], hv0.y, uv[jj].y);
                ffma2(acc[1][jj], hv1.x, uv[jj].x);
                ffma2(acc[1][jj], hv1.y, uv[jj].y);
            }
        }
#pragma unroll
        for (int i = 0; i < 2; ++i)
#pragma unroll
            for (int jj = 0; jj < 4; ++jj)
                red[wk * (16 * R_STR) + (wb + lb + 4 * i) * R_STR + ln + 8 * jj] =
                    lohi_sum(acc[i][jj]);
        __syncthreads();

        {
            float s = bu;
#pragma unroll
            for (int p = 0; p < 8; ++p)
                s += red[p * (16 * R_STR) + bi * R_STR + nl];
            const float h = hw_tanh(s + xwv);
            g_h3[(t + 1) & 1][hrow] = h;
            out1[orow + (size_t)(t + 1) * HH] = h;
            if (t == TT - 2) out2[hrow] = h;
        }
        __syncthreads();
        if (tid == 0) { __threadfence(); atomicAdd(cnt, 1u); }
    }
}

// =====================================================================
// launch
// =====================================================================
extern "C" void kernel_launch(void* const* d_in, const int* in_sizes, int n_in,
                              void* d_out, int out_size)
{
    const float* x  = (const float*)d_in[0];
    const float* W  = (const float*)d_in[1];
    const float* bW = (const float*)d_in[2];
    const float* U  = (const float*)d_in[3];
    const float* bU = (const float*)d_in[4];

    float* out1 = (float*)d_out;
    float* out2 = out1 + (size_t)BB * TT * HH;

    cudaFuncSetAttribute(scan_kernel,
                         cudaFuncAttributeMaxDynamicSharedMemorySize, SMEM_SCAN);

    split_kernel<<<2048, 256>>>(x, W);
    dim3 gm(HH / 128, (BB * TT) / 128);   // (8, 256)
    mma_kernel<<<gm, 256>>>(bW);
    scan_kernel<<<128, 512, SMEM_SCAN>>>(U, bU, out1, out2);
}

// round 16
// speedup vs baseline: 2.3813x; 1.2929x over previous
#include <cuda_runtime.h>
#include <cuda_bf16.h>
#include <cstdint>
#include <cstddef>

#define BB 64
#define TT 512
#define II 1024
#define HH 1024

typedef unsigned long long ull;

// ---------------- scratch (device globals; no cudaMalloc allowed) ----------------
__device__ float g_xw[(size_t)BB * TT * HH];   // 128 MiB: xw = x@W^T + bW
__device__ float g_h3[2][(size_t)BB * HH];     // ping-pong h3 exchange (fp32)
__device__ unsigned g_cnt[128];                // per-b-group counters (slot bt*32)
__device__ __nv_bfloat16 g_xhi[(size_t)BB * TT * II];
__device__ __nv_bfloat16 g_xlo[(size_t)BB * TT * II];
__device__ __nv_bfloat16 g_whi[(size_t)HH * II];
__device__ __nv_bfloat16 g_wlo[(size_t)HH * II];

// ---------------- helpers ----------------
__device__ __forceinline__ float hw_tanh(float x) {
    float r;
    asm("tanh.approx.f32 %0, %1;" : "=f"(r) : "f"(x));
    return r;
}
// HMMA m16n8k16 bf16 row.col, f32 accumulate (verified in R13)
__device__ __forceinline__ void mma16816(float* c, const uint32_t* a, const uint32_t* b) {
    asm volatile(
        "mma.sync.aligned.m16n8k16.row.col.f32.bf16.bf16.f32 "
        "{%0,%1,%2,%3}, {%4,%5,%6,%7}, {%8,%9}, {%0,%1,%2,%3};"
        : "+f"(c[0]), "+f"(c[1]), "+f"(c[2]), "+f"(c[3])
        : "r"(a[0]), "r"(a[1]), "r"(a[2]), "r"(a[3]), "r"(b[0]), "r"(b[1]));
}
__device__ __forceinline__ uint32_t pack_bf2(__nv_bfloat16 a, __nv_bfloat16 b) {
    __nv_bfloat162 t(a, b);
    return *(uint32_t*)&t;
}
__device__ __forceinline__ void split_bf(float v, __nv_bfloat16& hi, __nv_bfloat16& lo) {
    hi = __float2bfloat16(v);
    lo = __float2bfloat16(v - __bfloat162float(hi));
}

// =====================================================================
// Kernel 0: split x and W into hi/lo bf16; reset barrier counters.
// =====================================================================
__global__ __launch_bounds__(256) void split_kernel(
    const float* __restrict__ x, const float* __restrict__ W)
{
    if (blockIdx.x == 0 && threadIdx.x < 128) g_cnt[threadIdx.x] = 0u;
    const size_t stride = (size_t)gridDim.x * blockDim.x;
    const size_t i0 = (size_t)blockIdx.x * blockDim.x + threadIdx.x;

    const size_t NX4 = (size_t)BB * TT * II / 4;
    for (size_t p = i0; p < NX4; p += stride) {
        float4 v = ((const float4*)x)[p];
        __nv_bfloat16 h0, h1, h2, h3, l0, l1, l2, l3;
        split_bf(v.x, h0, l0); split_bf(v.y, h1, l1);
        split_bf(v.z, h2, l2); split_bf(v.w, h3, l3);
        ((uint32_t*)g_xhi)[2 * p]     = pack_bf2(h0, h1);
        ((uint32_t*)g_xhi)[2 * p + 1] = pack_bf2(h2, h3);
        ((uint32_t*)g_xlo)[2 * p]     = pack_bf2(l0, l1);
        ((uint32_t*)g_xlo)[2 * p + 1] = pack_bf2(l2, l3);
    }
    const size_t NW4 = (size_t)HH * II / 4;
    for (size_t p = i0; p < NW4; p += stride) {
        float4 v = ((const float4*)W)[p];
        __nv_bfloat16 h0, h1, h2, h3, l0, l1, l2, l3;
        split_bf(v.x, h0, l0); split_bf(v.y, h1, l1);
        split_bf(v.z, h2, l2); split_bf(v.w, h3, l3);
        ((uint32_t*)g_whi)[2 * p]     = pack_bf2(h0, h1);
        ((uint32_t*)g_whi)[2 * p + 1] = pack_bf2(h2, h3);
        ((uint32_t*)g_wlo)[2 * p]     = pack_bf2(l0, l1);
        ((uint32_t*)g_wlo)[2 * p + 1] = pack_bf2(l2, l3);
    }
}

// =====================================================================
// Kernel 1: xw = x@W^T + bW via mma.sync bf16 (unchanged from R13).
// =====================================================================
#define MS 40

__global__ __launch_bounds__(256, 2) void mma_kernel(const float* __restrict__ bW)
{
    __shared__ __nv_bfloat16 sA[2][128 * MS];
    __shared__ __nv_bfloat16 sB[2][128 * MS];

    const int tid = threadIdx.x;
    const int wid = tid >> 5, l = tid & 31;
    const int g = l >> 2, t = l & 3;
    const int wm = (wid & 1) * 64;
    const int wn = (wid >> 1) * 32;
    const int n_blk = blockIdx.x * 128, m_blk = blockIdx.y * 128;

    const __nv_bfloat16* Aptr[3] = { g_xhi, g_xhi, g_xlo };
    const __nv_bfloat16* Bptr[3] = { g_whi, g_wlo, g_whi };

    const int ar0 = tid >> 2, ag0 = (tid & 3) * 8;
    const int ar1 = (tid + 256) >> 2, ag1 = ag0;

    float acc[4][4][4];
#pragma unroll
    for (int i = 0; i < 4; ++i)
#pragma unroll
        for (int j = 0; j < 4; ++j)
#pragma unroll
            for (int q = 0; q < 4; ++q) acc[i][j][q] = 0.0f;

    {
        const __nv_bfloat16* ap = Aptr[0] + (size_t)m_blk * II;
        const __nv_bfloat16* bp = Bptr[0] + (size_t)n_blk * II;
        *(uint4*)&sA[0][ar0 * MS + ag0] = *(const uint4*)(ap + (size_t)ar0 * II + ag0);
        *(uint4*)&sA[0][ar1 * MS + ag1] = *(const uint4*)(ap + (size_t)ar1 * II + ag1);
        *(uint4*)&sB[0][ar0 * MS + ag0] = *(const uint4*)(bp + (size_t)ar0 * II + ag0);
        *(uint4*)&sB[0][ar1 * MS + ag1] = *(const uint4*)(bp + (size_t)ar1 * II + ag1);
    }
    __syncthreads();

    for (int c = 0; c < 96; ++c) {
        const int cur = c & 1, nxt = cur ^ 1;
        uint4 va0, va1, vb0, vb1;
        const bool more = (c + 1) < 96;
        if (more) {
            const int term = (c + 1) >> 5;
            const int ko = ((c + 1) & 31) * 32;
            const __nv_bfloat16* ap = Aptr[term] + (size_t)m_blk * II + ko;
            const __nv_bfloat16* bp = Bptr[term] + (size_t)n_blk * II + ko;
            va0 = *(const uint4*)(ap + (size_t)ar0 * II + ag0);
            va1 = *(const uint4*)(ap + (size_t)ar1 * II + ag1);
            vb0 = *(const uint4*)(bp + (size_t)ar0 * II + ag0);
            vb1 = *(const uint4*)(bp + (size_t)ar1 * II + ag1);
        }
#pragma unroll
        for (int ks = 0; ks < 2; ++ks) {
            const int kk = ks * 16;
            uint32_t af[4][4], bf[4][2];
#pragma unroll
            for (int mt = 0; mt < 4; ++mt) {
                const int row = wm + 16 * mt + g;
                af[mt][0] = *(const uint32_t*)&sA[cur][row * MS + kk + 2 * t];
                af[mt][1] = *(const uint32_t*)&sA[cur][(row + 8) * MS + kk + 2 * t];
                af[mt][2] = *(const uint32_t*)&sA[cur][row * MS + kk + 2 * t + 8];
                af[mt][3] = *(const uint32_t*)&sA[cur][(row + 8) * MS + kk + 2 * t + 8];
            }
#pragma unroll
            for (int nt = 0; nt < 4; ++nt) {
                const int rn = wn + 8 * nt + g;
                bf[nt][0] = *(const uint32_t*)&sB[cur][rn * MS + kk + 2 * t];
                bf[nt][1] = *(const uint32_t*)&sB[cur][rn * MS + kk + 2 * t + 8];
            }
#pragma unroll
            for (int mt = 0; mt < 4; ++mt)
#pragma unroll
                for (int nt = 0; nt < 4; ++nt)
                    mma16816(acc[mt][nt], af[mt], bf[nt]);
        }
        if (more) {
            *(uint4*)&sA[nxt][ar0 * MS + ag0] = va0;
            *(uint4*)&sA[nxt][ar1 * MS + ag1] = va1;
            *(uint4*)&sB[nxt][ar0 * MS + ag0] = vb0;
            *(uint4*)&sB[nxt][ar1 * MS + ag1] = vb1;
        }
        __syncthreads();
    }

#pragma unroll
    for (int nt = 0; nt < 4; ++nt) {
        const int col = n_blk + wn + 8 * nt + 2 * t;
        const float2 bw2 = *(const float2*)&bW[col];
#pragma unroll
        for (int mt = 0; mt < 4; ++mt) {
            const int m0 = m_blk + wm + 16 * mt + g;
            float2 o0, o1;
            o0.x = acc[mt][nt][0] + bw2.x; o0.y = acc[mt][nt][1] + bw2.y;
            o1.x = acc[mt][nt][2] + bw2.x; o1.y = acc[mt][nt][3] + bw2.y;
            *(float2*)&g_xw[(size_t)m0 * HH + col] = o0;
            *(float2*)&g_xw[(size_t)(m0 + 8) * HH + col] = o1;
        }
    }
}

// =====================================================================
// Kernel 2: persistent scan — HMMA Phase B with hi/lo bf16 split.
// 128 CTAs = 4 b-groups x 32 n-tiles, 512 threads (16 warps).
// smem: Uc bf16 [32][2056] = [U_hi(k<1024) | U_lo(k>=1024)] (once),
//       h3c bf16 [16][2056] = [h_hi | h_lo] (per step),
//       red f32 [16][16][32].
// Effective K = 3072 (hh, lh, hl) = 192 k16-chunks; warp w does 12.
// Fragments: plain LDS.32, stride 2056 -> banks (4g+t) distinct.
// =====================================================================
#define SC_STR 2056
#define SC_BF16 (48 * SC_STR)                    // Uc + h3c in bf16 elems
#define SMEM_SCAN (SC_BF16 * 2 + 16 * 512 * 4)   // 230144 bytes

__global__ __launch_bounds__(512, 1) void scan_kernel(
    const float* __restrict__ U, const float* __restrict__ bU,
    float* __restrict__ out1, float* __restrict__ out2)
{
    extern __shared__ char sm[];
    __nv_bfloat16* Uc  = (__nv_bfloat16*)sm;            // [32][SC_STR]
    __nv_bfloat16* h3c = Uc + 32 * SC_STR;              // [16][SC_STR]
    float* red = (float*)(sm + (size_t)SC_BF16 * 2);    // [16][16][32]

    const int tid = threadIdx.x;
    const int bt = blockIdx.x >> 5, nt_blk = blockIdx.x & 31;
    const int b0 = bt * 16, n0 = nt_blk * 32;
    unsigned* cnt = &g_cnt[bt * 32];

    const int w = tid >> 5, l = tid & 31;
    const int g = l >> 2, t = l & 3;

    // ---- convert U slice (rows n0..n0+31) into Uc, once ----
#pragma unroll
    for (int i = 0; i < 8; ++i) {
        const int gi = i * 512 + tid;           // granule of 8 floats
        const int row = gi >> 7, k = (gi & 127) * 8;
        const float* up = &U[(size_t)(n0 + row) * HH + k];
        float4 a = *(const float4*)up;
        float4 b = *(const float4*)(up + 4);
        __nv_bfloat16 h[8], lo[8];
        split_bf(a.x, h[0], lo[0]); split_bf(a.y, h[1], lo[1]);
        split_bf(a.z, h[2], lo[2]); split_bf(a.w, h[3], lo[3]);
        split_bf(b.x, h[4], lo[4]); split_bf(b.y, h[5], lo[5]);
        split_bf(b.z, h[6], lo[6]); split_bf(b.w, h[7], lo[7]);
        uint4 vh = { pack_bf2(h[0], h[1]),  pack_bf2(h[2], h[3]),
                     pack_bf2(h[4], h[5]),  pack_bf2(h[6], h[7]) };
        uint4 vl = { pack_bf2(lo[0], lo[1]), pack_bf2(lo[2], lo[3]),
                     pack_bf2(lo[4], lo[5]), pack_bf2(lo[6], lo[7]) };
        *(uint4*)&Uc[row * SC_STR + k]        = vh;
        *(uint4*)&Uc[row * SC_STR + 1024 + k] = vl;
    }

    // output mapping: one element per thread
    const int bi = tid >> 5;
    const int nl = tid & 31;
    const float bu = bU[n0 + nl];
    const size_t orow = (size_t)(b0 + bi) * TT * HH + n0 + nl;
    const size_t hrow = (size_t)(b0 + bi) * HH + n0 + nl;

    // staging mapping: thread stages row = tid>>5, k-granules l + 32i
    const int srow = tid >> 5;

    // ---- bootstrap: h3[0] = tanh(xw[0]) ----
    {
        float h = hw_tanh(g_xw[orow]);
        g_h3[0][hrow] = h;
        out1[orow] = h;
    }
    __syncthreads();
    if (tid == 0) { __threadfence(); atomicAdd(cnt, 1u); }

    for (int tstep = 0; tstep < TT - 1; ++tstep) {
        // prefetch xw[t+1] (issues before barrier wait)
        const float xwv = g_xw[orow + (size_t)(tstep + 1) * HH];

        // ---- wait for h3[t] from all 32 CTAs of this b-group ----
        if (tid == 0) {
            const unsigned target = 32u * (unsigned)(tstep + 1);
            while (*(volatile unsigned*)cnt < target) {}
            __threadfence();
        }
        __syncthreads();

        // ---- stage h3[t] -> h3c hi/lo (thread: row srow, 4 granules) ----
        {
            const float* hsrc = &g_h3[tstep & 1][(size_t)(b0 + srow) * HH];
#pragma unroll
            for (int i = 0; i < 4; ++i) {
                const int k = l * 8 + i * 256;
                float4 a = *(const float4*)(hsrc + k);
                float4 b = *(const float4*)(hsrc + k + 4);
                __nv_bfloat16 h[8], lo[8];
                split_bf(a.x, h[0], lo[0]); split_bf(a.y, h[1], lo[1]);
                split_bf(a.z, h[2], lo[2]); split_bf(a.w, h[3], lo[3]);
                split_bf(b.x, h[4], lo[4]); split_bf(b.y, h[5], lo[5]);
                split_bf(b.z, h[6], lo[6]); split_bf(b.w, h[7], lo[7]);
                uint4 vh = { pack_bf2(h[0], h[1]),  pack_bf2(h[2], h[3]),
                             pack_bf2(h[4], h[5]),  pack_bf2(h[6], h[7]) };
                uint4 vl = { pack_bf2(lo[0], lo[1]), pack_bf2(lo[2], lo[3]),
                             pack_bf2(lo[4], lo[5]), pack_bf2(lo[6], lo[7]) };
                *(uint4*)&h3c[srow * SC_STR + k]        = vh;
                *(uint4*)&h3c[srow * SC_STR + 1024 + k] = vl;
            }
        }
        __syncthreads();

        // ---- Phase B: 12 k16-chunks of the effective K=3072 GEMM ----
        float acc[4][4];
#pragma unroll
        for (int i = 0; i < 4; ++i)
#pragma unroll
            for (int q = 0; q < 4; ++q) acc[i][q] = 0.0f;

#pragma unroll
        for (int ci = 0; ci < 12; ++ci) {
            const int c = w * 12 + ci;              // 0..191
            const int term = c >> 6;                // 0:hh 1:lh 2:hl
            const int kk = (c & 63) * 16;
            const int aoff = (term == 1 ? 1024 : 0) + kk;
            const int boff = (term == 2 ? 1024 : 0) + kk;

            uint32_t af[4];
            af[0] = *(const uint32_t*)&h3c[g * SC_STR + aoff + 2 * t];
            af[1] = *(const uint32_t*)&h3c[(g + 8) * SC_STR + aoff + 2 * t];
            af[2] = *(const uint32_t*)&h3c[g * SC_STR + aoff + 2 * t + 8];
            af[3] = *(const uint32_t*)&h3c[(g + 8) * SC_STR + aoff + 2 * t + 8];
#pragma unroll
            for (int nt = 0; nt < 4; ++nt) {
                uint32_t bf[2];
                bf[0] = *(const uint32_t*)&Uc[(8 * nt + g) * SC_STR + boff + 2 * t];
                bf[1] = *(const uint32_t*)&Uc[(8 * nt + g) * SC_STR + boff + 2 * t + 8];
                mma16816(acc[nt], af, bf);
            }
        }

        // ---- store 16x32 partial (rows g, g+8; cols 8nt+2t..+1) ----
#pragma unroll
        for (int nt = 0; nt < 4; ++nt) {
            float2 p0 = { acc[nt][0], acc[nt][1] };
            float2 p1 = { acc[nt][2], acc[nt][3] };
            *(float2*)&red[w * 512 + g * 32 + 8 * nt + 2 * t] = p0;
            *(float2*)&red[w * 512 + (g + 8) * 32 + 8 * nt + 2 * t] = p1;
        }
        __syncthreads();

        // ---- reduce 16 partials, fuse bias + xw + tanh, publish ----
        {
            float s0 = bu, s1 = 0.0f;
#pragma unroll
            for (int p = 0; p < 16; p += 2) {
                s0 += red[p * 512 + bi * 32 + nl];
                s1 += red[(p + 1) * 512 + bi * 32 + nl];
            }
            const float h = hw_tanh(s0 + s1 + xwv);
            g_h3[(tstep + 1) & 1][hrow] = h;
            out1[orow + (size_t)(tstep + 1) * HH] = h;
            if (tstep == TT - 2) out2[hrow] = h;
        }
        __syncthreads();
        if (tid == 0) { __threadfence(); atomicAdd(cnt, 1u); }
    }
}

// =====================================================================
// launch
// =====================================================================
extern "C" void kernel_launch(void* const* d_in, const int* in_sizes, int n_in,
                              void* d_out, int out_size)
{
    const float* x  = (const float*)d_in[0];
    const float* W  = (const float*)d_in[1];
    const float* bW = (const float*)d_in[2];
    const float* U  = (const float*)d_in[3];
    const float* bU = (const float*)d_in[4];

    float* out1 = (float*)d_out;
    float* out2 = out1 + (size_t)BB * TT * HH;

    cudaFuncSetAttribute(scan_kernel,
                         cudaFuncAttributeMaxDynamicSharedMemorySize, SMEM_SCAN);

    split_kernel<<<2048, 256>>>(x, W);
    dim3 gm(HH / 128, (BB * TT) / 128);   // (8, 256)
    mma_kernel<<<gm, 256>>>(bW);
    scan_kernel<<<128, 512, SMEM_SCAN>>>(U, bU, out1, out2);
}